// round 16
// baseline (speedup 1.0000x reference)
#include <cuda_runtime.h>
#include <cuda_fp16.h>
#include <cstdint>
#include <math.h>

#define Bsz 64
#define Tt  512
#define Din 256
#define Hs  1024
#define G4  4096
#define MROWS (Tt*Bsz)
#define NBLK_REC 128
#define WSROW 1032
#define GS 3
#define GSTRIDE 40
#define STAGEH (128*GSTRIDE)
#define RTHREADS 384
#define SET32 (32*17)           // half2 per partial set (32 rows x 17)
// 12 sets: (grp*4 + ksl)

// persistent scratch
__device__ __half g_xgh[(size_t)MROWS * G4];     // [T][B][u*4+g] gate-interleaved
__device__ __half g_h0buf[2][Bsz * Hs];          // layer-0 hidden (physpos layout)
__device__ __half g_h1buf[2][Bsz * Hs];          // layer-1 hidden (physpos layout)
__device__ __half g_xh[(size_t)Bsz * Tt * Din];
__device__ __half g_w0h[(size_t)G4 * Din];
__device__ unsigned g_barcnt;                    // prologue barrier
__device__ unsigned g_bargen;
__device__ unsigned g_bcnt[2];                   // per-half phase barriers
__device__ unsigned g_bgen[2];

// ---------------------------------------------------------------- helpers
__device__ __forceinline__ void mma_f16(float* d, const unsigned* a, unsigned b0, unsigned b1) {
    asm volatile(
        "mma.sync.aligned.m16n8k16.row.col.f32.f16.f16.f32 "
        "{%0,%1,%2,%3},{%4,%5,%6,%7},{%8,%9},{%0,%1,%2,%3};"
        : "+f"(d[0]), "+f"(d[1]), "+f"(d[2]), "+f"(d[3])
        : "r"(a[0]), "r"(a[1]), "r"(a[2]), "r"(a[3]), "r"(b0), "r"(b1));
}

__device__ __forceinline__ void cp16(unsigned saddr, const void* g) {
    asm volatile("cp.async.cg.shared.global [%0], [%1], 16;" :: "r"(saddr), "l"(g));
}

__device__ __forceinline__ int perm16(int c) {
    return (c < 8) ? ((c >> 1) * 4 + (c & 1)) : (((c - 8) >> 1) * 4 + 2 + (c & 1));
}
__device__ __forceinline__ int physpos(int u) {
    int blk = u >> 4;
    int o = perm16(u & 15);
    int tg = o >> 2, inner = o & 3;
    return (blk >> 1) * 32 + tg * 8 + (blk & 1) * 4 + inner;
}

__device__ __forceinline__ float sigf(float x)  { return __fdividef(1.f, 1.f + __expf(-x)); }
__device__ __forceinline__ float tanhf_(float x){ return __fdividef(2.f, 1.f + __expf(-2.f * x)) - 1.f; }

// prologue barrier (r15 canonical)
__device__ __forceinline__ void grid_barrier(unsigned nblk, unsigned expect) {
    __syncthreads();
    if (threadIdx.x == 0) {
        asm volatile("fence.acq_rel.gpu;" ::: "memory");
        if (atomicAdd(&g_barcnt, 1u) == nblk - 1u) {
            g_barcnt = 0;
            asm volatile("st.release.gpu.global.u32 [%0], %1;" :: "l"(&g_bargen), "r"(expect) : "memory");
        }
        unsigned cur;
        do {
            asm volatile("ld.acquire.gpu.global.u32 %0, [%1];" : "=r"(cur) : "l"(&g_bargen) : "memory");
        } while (cur < expect);
    }
    __syncthreads();
}

// per-half phase barrier: DELAYED wait (arrive at phase end; wait at next same-half phase).
__device__ __forceinline__ void half_wait(int half, unsigned target) {
    if (threadIdx.x == 0) {
        unsigned cur;
        do {
            asm volatile("ld.acquire.gpu.global.u32 %0, [%1];" : "=r"(cur) : "l"(&g_bgen[half]) : "memory");
        } while (cur < target);
    }
    __syncthreads();
}
__device__ __forceinline__ void half_arrive(int half, unsigned round) {
    __syncthreads();            // all warps' global writes for this phase done
    if (threadIdx.x == 0) {
        unsigned old;
        asm volatile("atom.release.gpu.global.add.u32 %0, [%1], %2;"
                     : "=r"(old) : "l"(&g_bcnt[half]), "r"(1u) : "memory");
        if (old == NBLK_REC - 1u) {
            g_bcnt[half] = 0;   // ordered before the release store below
            asm volatile("st.release.gpu.global.u32 [%0], %1;" :: "l"(&g_bgen[half]), "r"(round) : "memory");
        }
    }
}

// ---------------------------------------------------------------- fp32 -> fp16 (+barrier reset)
__global__ void tohalf_kernel(const float* __restrict__ src, __half* __restrict__ dst, int n)
{
    if (blockIdx.x == 0 && threadIdx.x == 0) {
        g_barcnt = 0; g_bargen = 0;
        g_bcnt[0] = 0; g_bcnt[1] = 0;
        g_bgen[0] = 0; g_bgen[1] = 0;
    }
    for (int i = blockIdx.x * blockDim.x + threadIdx.x; i < n; i += gridDim.x * blockDim.x)
        dst[i] = __float2half_rn(src[i]);
}

// ---------------------------------------------------------------- xg0 GEMM (gate-interleaved epilogue)
#define GSMEM (GS * STAGEH * 2 * 2)

__global__ __launch_bounds__(256, 2)
void gemm_xg_kernel(const __half* __restrict__ A, const __half* __restrict__ W,
                    const float* __restrict__ bias, int K)
{
    extern __shared__ __half gsm[];
    __half* As = gsm;
    __half* Bs = gsm + GS * STAGEH;

    const int tid  = threadIdx.x;
    const int lane = tid & 31, warp = tid >> 5;
    const int gid  = lane >> 2, tig = lane & 3;
    const int wm   = warp >> 1, wn = warp & 1;
    const int bm   = blockIdx.y * 128, bn = blockIdx.x * 128;

    const __half* ga[2]; const __half* gb[2]; int soff[2];
    #pragma unroll
    for (int j = 0; j < 2; ++j) {
        int i = tid + j * 256;
        int row = i >> 2, seg = (i & 3) * 8;
        int rm = bm + row;
        ga[j] = A + ((size_t)(rm & 63) * Tt + (rm >> 6)) * Din + seg;
        gb[j] = W + (size_t)(bn + row) * K + seg;
        soff[j] = row * GSTRIDE + seg;
    }
    unsigned sA = (unsigned)__cvta_generic_to_shared(As);
    unsigned sB = (unsigned)__cvta_generic_to_shared(Bs);

    const int nch = K / 32;

    auto stage = [&](int s, int k0) {
        #pragma unroll
        for (int j = 0; j < 2; ++j) {
            cp16(sA + (s * STAGEH + soff[j]) * 2, ga[j] + k0);
            cp16(sB + (s * STAGEH + soff[j]) * 2, gb[j] + k0);
        }
        asm volatile("cp.async.commit_group;");
    };

    stage(0, 0);
    stage(1, 32);

    float acc[2][8][4] = {};

    for (int c = 0; c < nch; ++c) {
        if (c + 1 < nch) asm volatile("cp.async.wait_group 1;");
        else             asm volatile("cp.async.wait_group 0;");
        __syncthreads();
        if (c + 2 < nch) stage((c + 2) % GS, (c + 2) * 32);

        const __half* Asl = As + (c % GS) * STAGEH;
        const __half* Bsl = Bs + (c % GS) * STAGEH;
        #pragma unroll
        for (int s = 0; s < 2; ++s) {
            int kk = s * 16;
            unsigned a[2][4];
            #pragma unroll
            for (int mt = 0; mt < 2; ++mt) {
                int m = wm * 32 + mt * 16 + gid;
                a[mt][0] = *(const unsigned*)&Asl[m * GSTRIDE + kk + 2 * tig];
                a[mt][1] = *(const unsigned*)&Asl[(m + 8) * GSTRIDE + kk + 2 * tig];
                a[mt][2] = *(const unsigned*)&Asl[m * GSTRIDE + kk + 8 + 2 * tig];
                a[mt][3] = *(const unsigned*)&Asl[(m + 8) * GSTRIDE + kk + 8 + 2 * tig];
            }
            #pragma unroll
            for (int nt = 0; nt < 8; ++nt) {
                int n = wn * 64 + nt * 8 + gid;
                unsigned b0 = *(const unsigned*)&Bsl[n * GSTRIDE + kk + 2 * tig];
                unsigned b1 = *(const unsigned*)&Bsl[n * GSTRIDE + kk + 8 + 2 * tig];
                mma_f16(acc[0][nt], a[0], b0, b1);
                mma_f16(acc[1][nt], a[1], b0, b1);
            }
        }
    }

    #pragma unroll
    for (int mt = 0; mt < 2; ++mt) {
        #pragma unroll
        for (int nt = 0; nt < 8; ++nt) {
            int row = bm + wm * 32 + mt * 16 + gid;
            int col = bn + wn * 64 + nt * 8 + 2 * tig;
            float bc0 = bias[col], bc1 = bias[col + 1];
            int rm0 = (col & 1023) * 4 + (col >> 10);
            int rm1 = ((col + 1) & 1023) * 4 + ((col + 1) >> 10);
            g_xgh[(size_t)row * G4 + rm0] = __float2half_rn(acc[mt][nt][0] + bc0);
            g_xgh[(size_t)row * G4 + rm1] = __float2half_rn(acc[mt][nt][1] + bc1);
            g_xgh[(size_t)(row + 8) * G4 + rm0] = __float2half_rn(acc[mt][nt][2] + bc0);
            g_xgh[(size_t)(row + 8) * G4 + rm1] = __float2half_rn(acc[mt][nt][3] + bc1);
        }
    }
}

// ---------------------------------------------------------------- fused 2-layer recurrence
// Batch-split pipelined: phases (s, half). 12 warps = 3 groups x 4 K-slices (m32n32k256).
// Per-half barrier counters: arrive at phase end, wait at next same-half phase -> the
// other half's compute hides release propagation + skew.
#define RSMEM (96*WSROW*2 + 12*SET32*4)

__global__ __launch_bounds__(RTHREADS, 1)
void rec2_kernel(const float* __restrict__ Whh0, const float* __restrict__ Wih1,
                 const float* __restrict__ Whh1, const float* __restrict__ b1)
{
    extern __shared__ unsigned char smraw[];
    __half*  Ws   = (__half*)smraw;                        // [3][32][WSROW]
    __half2* scr2 = (__half2*)(smraw + 96 * WSROW * 2);    // [12][32][17]

    const int tid  = threadIdx.x;
    const int lane = tid & 31, warp = tid >> 5;
    const int gid  = lane >> 2, tig = lane & 3;
    const int grp  = warp >> 2;            // 0:Whh0 1:Wih1 2:Whh1
    const int ksl  = warp & 3;             // K4 slice
    const int u0   = blockIdx.x * 8;

    // one-time: 3 weight slices -> smem fp16 (rows l = g*8+n)
    {
        const float* srcs[3] = {Whh0, Wih1, Whh1};
        for (int sl = 0; sl < 3; ++sl) {
            const float* src = srcs[sl];
            __half* dst = Ws + sl * 32 * WSROW;
            for (int i = tid; i < 32 * Hs; i += RTHREADS) {
                int l = i >> 10, k = i & 1023;
                int g = l >> 3, n = l & 7;
                dst[l * WSROW + k] = __float2half_rn(src[(size_t)(g * Hs + u0 + n) * Hs + k]);
            }
        }
    }
    // zero h "minus-one" buffers: h0[-1] parity 1; h1[-1] parity 0
    for (int i = tid; i < 512; i += RTHREADS) {
        int b = i >> 3, uu = i & 7;
        int col = physpos(u0 + uu);
        g_h0buf[1][b * Hs + col] = __float2half_rn(0.f);
        g_h1buf[0][b * Hs + col] = __float2half_rn(0.f);
    }

    // ldmatrix lane pointers (K-slice k256 baked in)
    const int ltile = lane >> 3, lrow = lane & 7;
    unsigned lp0, lp1;
    {
        const __half* wsl = Ws + grp * 32 * WSROW + ksl * 256;
        const __half* p0 = wsl + (size_t)(((ltile >> 1)) * 8 + lrow) * WSROW + (ltile & 1) * 8;
        const __half* p1 = wsl + (size_t)((2 + (ltile >> 1)) * 8 + lrow) * WSROW + (ltile & 1) * 8;
        lp0 = (unsigned)__cvta_generic_to_shared(p0);
        lp1 = (unsigned)__cvta_generic_to_shared(p1);
    }

    const int re = (warp & 3) * 8 + gid;    // epilogue row within half (0..31)
    float cst[2][2] = {{0.f, 0.f}, {0.f, 0.f}};   // [half][cell]
    float bi1[4][2];
    if (grp == 2) {
        #pragma unroll
        for (int g = 0; g < 4; ++g) {
            bi1[g][0] = b1[g * Hs + u0 + 2 * tig];
            bi1[g][1] = b1[g * Hs + u0 + 2 * tig + 1];
        }
    }
    const int wpos = physpos(u0 + 2 * tig);

    grid_barrier(NBLK_REC, 1);   // init visibility

    for (int s = 0; s <= Tt; ++s) {
        #pragma unroll 1
        for (int half = 0; half < 2; ++half) {
            const int R0 = half * 32;

            half_wait(half, (unsigned)s);

            // xg prefetch (grp0, 1 row per thread)
            uint4 px;
            const int grow = R0 + re;
            if (grp == 0 && s < Tt)
                px = *(const uint4*)(g_xgh + ((size_t)s * Bsz + grow) * G4 + 4 * (u0 + 2 * tig));

            const bool doM = (grp == 0) ? (s < Tt) : (s >= 1);
            float acc[4][2][4] = {};    // [gate][m16 tile][frag]

            if (doM) {
                const __half* hp = (grp == 2) ? g_h1buf[(s + 1) & 1] : g_h0buf[(s + 1) & 1];
                const uint4* aP0 = (const uint4*)(hp + (size_t)(R0 + gid)      * Hs + ksl * 256) + tig;
                const uint4* aP1 = (const uint4*)(hp + (size_t)(R0 + gid + 8)  * Hs + ksl * 256) + tig;
                const uint4* aP2 = (const uint4*)(hp + (size_t)(R0 + gid + 16) * Hs + ksl * 256) + tig;
                const uint4* aP3 = (const uint4*)(hp + (size_t)(R0 + gid + 24) * Hs + ksl * 256) + tig;
                #pragma unroll
                for (int j = 0; j < 8; ++j) {
                    uint4 v0 = aP0[4 * j], v1 = aP1[4 * j], v2 = aP2[4 * j], v3 = aP3[4 * j];
                    unsigned b0, b1r, b2, b3;
                    {   // kstep 2j
                        unsigned a0[4] = {v0.x, v1.x, v0.y, v1.y};
                        unsigned a1[4] = {v2.x, v3.x, v2.y, v3.y};
                        asm volatile("ldmatrix.sync.aligned.m8n8.x4.shared.b16 {%0,%1,%2,%3}, [%4];"
                                     : "=r"(b0), "=r"(b1r), "=r"(b2), "=r"(b3) : "r"(lp0 + j * 64));
                        mma_f16(acc[0][0], a0, b0, b1r); mma_f16(acc[0][1], a1, b0, b1r);
                        mma_f16(acc[1][0], a0, b2, b3);  mma_f16(acc[1][1], a1, b2, b3);
                        asm volatile("ldmatrix.sync.aligned.m8n8.x4.shared.b16 {%0,%1,%2,%3}, [%4];"
                                     : "=r"(b0), "=r"(b1r), "=r"(b2), "=r"(b3) : "r"(lp1 + j * 64));
                        mma_f16(acc[2][0], a0, b0, b1r); mma_f16(acc[2][1], a1, b0, b1r);
                        mma_f16(acc[3][0], a0, b2, b3);  mma_f16(acc[3][1], a1, b2, b3);
                    }
                    {   // kstep 2j+1
                        unsigned a0[4] = {v0.z, v1.z, v0.w, v1.w};
                        unsigned a1[4] = {v2.z, v3.z, v2.w, v3.w};
                        asm volatile("ldmatrix.sync.aligned.m8n8.x4.shared.b16 {%0,%1,%2,%3}, [%4];"
                                     : "=r"(b0), "=r"(b1r), "=r"(b2), "=r"(b3) : "r"(lp0 + j * 64 + 32));
                        mma_f16(acc[0][0], a0, b0, b1r); mma_f16(acc[0][1], a1, b0, b1r);
                        mma_f16(acc[1][0], a0, b2, b3);  mma_f16(acc[1][1], a1, b2, b3);
                        asm volatile("ldmatrix.sync.aligned.m8n8.x4.shared.b16 {%0,%1,%2,%3}, [%4];"
                                     : "=r"(b0), "=r"(b1r), "=r"(b2), "=r"(b3) : "r"(lp1 + j * 64 + 32));
                        mma_f16(acc[2][0], a0, b0, b1r); mma_f16(acc[2][1], a1, b0, b1r);
                        mma_f16(acc[3][0], a0, b2, b3);  mma_f16(acc[3][1], a1, b2, b3);
                    }
                }
                // partials -> smem set (grp*4 + ksl), rows mt*16+gid (+8)
                __half2* sc = scr2 + (grp * 4 + ksl) * SET32;
                #pragma unroll
                for (int g = 0; g < 4; ++g) {
                    #pragma unroll
                    for (int mt = 0; mt < 2; ++mt) {
                        int row = mt * 16 + gid;
                        sc[row * 17 + g * 4 + tig]       = __floats2half2_rn(acc[g][mt][0], acc[g][mt][1]);
                        sc[(row + 8) * 17 + g * 4 + tig] = __floats2half2_rn(acc[g][mt][2], acc[g][mt][3]);
                    }
                }
            }

            if (grp == 0) {
                if (s < Tt) {
                    asm volatile("bar.sync 1, 128;" ::: "memory");
                    float2 G[4];
                    #pragma unroll
                    for (int g = 0; g < 4; ++g) {
                        float gx = 0.f, gy = 0.f;
                        #pragma unroll
                        for (int k = 0; k < 4; ++k) {
                            __half2 p = scr2[k * SET32 + re * 17 + g * 4 + tig];
                            gx += __low2float(p); gy += __high2float(p);
                        }
                        G[g] = make_float2(gx, gy);
                    }
                    __half* hn = g_h0buf[s & 1];
                    float hv[2];
                    __half2 vlo0 = *reinterpret_cast<__half2*>(&px.x);   // unit0 (i,f)
                    __half2 vhi0 = *reinterpret_cast<__half2*>(&px.y);   // unit0 (g,o)
                    __half2 vlo1 = *reinterpret_cast<__half2*>(&px.z);   // unit1 (i,f)
                    __half2 vhi1 = *reinterpret_cast<__half2*>(&px.w);   // unit1 (g,o)
                    #pragma unroll
                    for (int fc = 0; fc < 2; ++fc) {
                        __half2 vlo = fc ? vlo1 : vlo0;
                        __half2 vhi = fc ? vhi1 : vhi0;
                        float gi = (fc ? G[0].y : G[0].x) + __low2float(vlo);
                        float gf = (fc ? G[1].y : G[1].x) + __high2float(vlo);
                        float gg = (fc ? G[2].y : G[2].x) + __low2float(vhi);
                        float go = (fc ? G[3].y : G[3].x) + __high2float(vhi);
                        gi = sigf(gi); gf = sigf(gf); gg = tanhf_(gg); go = sigf(go);
                        float c = gf * cst[half][fc] + gi * gg;
                        cst[half][fc] = c;
                        hv[fc] = go * tanhf_(c);
                    }
                    *reinterpret_cast<__half2*>(hn + (size_t)grow * Hs + wpos) = __floats2half2_rn(hv[0], hv[1]);
                }
            } else {
                if (s >= 1) {
                    asm volatile("bar.sync 2, 256;" ::: "memory");
                    if (grp == 2) {
                        float2 G[4];
                        #pragma unroll
                        for (int g = 0; g < 4; ++g) {
                            float gx = 0.f, gy = 0.f;
                            #pragma unroll
                            for (int k = 0; k < 8; ++k) {   // grp1 sets 4-7, grp2 sets 8-11
                                __half2 p = scr2[(4 + k) * SET32 + re * 17 + g * 4 + tig];
                                gx += __low2float(p); gy += __high2float(p);
                            }
                            G[g] = make_float2(gx, gy);
                        }
                        __half* hn = g_h1buf[s & 1];     // h1[s-1]
                        float hv[2];
                        #pragma unroll
                        for (int fc = 0; fc < 2; ++fc) {
                            float gi = (fc ? G[0].y : G[0].x) + bi1[0][fc];
                            float gf = (fc ? G[1].y : G[1].x) + bi1[1][fc];
                            float gg = (fc ? G[2].y : G[2].x) + bi1[2][fc];
                            float go = (fc ? G[3].y : G[3].x) + bi1[3][fc];
                            gi = sigf(gi); gf = sigf(gf); gg = tanhf_(gg); go = sigf(go);
                            float c = gf * cst[half][fc] + gi * gg;
                            cst[half][fc] = c;
                            hv[fc] = go * tanhf_(c);
                        }
                        *reinterpret_cast<__half2*>(hn + (size_t)grow * Hs + wpos) = __floats2half2_rn(hv[0], hv[1]);
                    }
                }
            }

            half_arrive(half, (unsigned)(s + 1));
        }
    }
}

// ---------------------------------------------------------------- final FC (physpos h)
__global__ void fc_kernel(const float* __restrict__ Wfc, const float* __restrict__ bfc,
                          float* __restrict__ out)
{
    int b = blockIdx.x;
    const __half* h = g_h1buf[0] + b * Hs;   // h1[511] written at s=512 -> parity 0
    float s = 0.f;
    for (int k = threadIdx.x; k < Hs; k += 128)
        s += __half2float(h[physpos(k)]) * Wfc[k];
    #pragma unroll
    for (int o = 16; o > 0; o >>= 1)
        s += __shfl_down_sync(0xffffffffu, s, o);
    __shared__ float sm[4];
    if ((threadIdx.x & 31) == 0) sm[threadIdx.x >> 5] = s;
    __syncthreads();
    if (threadIdx.x == 0)
        out[b] = sm[0] + sm[1] + sm[2] + sm[3] + bfc[0];
}

// ---------------------------------------------------------------- launch
extern "C" void kernel_launch(void* const* d_in, const int* in_sizes, int n_in,
                              void* d_out, int out_size)
{
    (void)in_sizes; (void)n_in; (void)out_size;
    const float* x    = (const float*)d_in[0];
    const float* Wih0 = (const float*)d_in[1];
    const float* Whh0 = (const float*)d_in[2];
    const float* b0   = (const float*)d_in[3];
    const float* Wih1 = (const float*)d_in[4];
    const float* Whh1 = (const float*)d_in[5];
    const float* b1   = (const float*)d_in[6];
    const float* Wfc  = (const float*)d_in[7];
    const float* bfc  = (const float*)d_in[8];
    float* out = (float*)d_out;

    cudaFuncSetAttribute(rec2_kernel, cudaFuncAttributeMaxDynamicSharedMemorySize, RSMEM);
    cudaFuncSetAttribute(gemm_xg_kernel, cudaFuncAttributeMaxDynamicSharedMemorySize, GSMEM);

    __half* xh  = nullptr; cudaGetSymbolAddress((void**)&xh,  g_xh);
    __half* w0h = nullptr; cudaGetSymbolAddress((void**)&w0h, g_w0h);

    tohalf_kernel<<<4096, 256>>>(x,    xh,  Bsz * Tt * Din);
    tohalf_kernel<<<1024, 256>>>(Wih0, w0h, G4 * Din);

    dim3 grid(G4 / 128, MROWS / 128);
    gemm_xg_kernel<<<grid, 256, GSMEM>>>(xh, w0h, b0, Din);
    rec2_kernel<<<NBLK_REC, RTHREADS, RSMEM>>>(Whh0, Wih1, Whh1, b1);
    fc_kernel<<<Bsz, 128>>>(Wfc, bfc, out);
}